// round 1
// baseline (speedup 1.0000x reference)
#include <cuda_runtime.h>
#include <mma.h>

using namespace nvcuda;

// BinaryLinear: out[M,N] = x[M,K] @ (sign(W)*alpha)[N,K]^T + b[N]
// M=8192 (derived), N=4096, K=4096. fp32 in/out, tf32 tensor-core compute.
//
// R0 baseline: wmma tf32 tiled GEMM (legacy HMMA path).
//   CTA tile 128x128, BK=32, 8 warps (2x4), warp tile 64x32.
//   Binarization (sign(W)*alpha) fused into B-tile SMEM store.
//   Bias added by a second elementwise kernel.

#define N_DIM 4096
#define K_DIM 4096
#define BM 128
#define BN 128
#define BK 32
#define SPAD 4                 // SMEM row stride = BK+SPAD = 36 (mult of 4 for wmma ldm)
#define SLD (BK + SPAD)

__global__ __launch_bounds__(256, 2)
void bgemm_tf32(const float* __restrict__ x,
                const float* __restrict__ W,
                const float* __restrict__ alpha,
                float* __restrict__ out)
{
    __shared__ float As[BM][SLD];
    __shared__ float Bs[BN][SLD];

    const int tid  = threadIdx.x;
    const int warp = tid >> 5;
    const int wm   = warp & 1;    // 0..1 -> 64-row slab
    const int wn   = warp >> 1;   // 0..3 -> 32-col slab

    const int m_cta = blockIdx.y * BM;
    const int n_cta = blockIdx.x * BN;

    wmma::fragment<wmma::accumulator, 16, 16, 8, float> c[4][2];
#pragma unroll
    for (int i = 0; i < 4; i++)
#pragma unroll
        for (int j = 0; j < 2; j++)
            wmma::fill_fragment(c[i][j], 0.0f);

    for (int kt = 0; kt < K_DIM; kt += BK) {
        // ---- load A tile: 128 rows x 32 cols, as 1024 float4 across 256 threads ----
#pragma unroll
        for (int i = 0; i < 4; i++) {
            int f  = tid + i * 256;
            int r  = f >> 3;          // row in tile
            int c4 = f & 7;           // float4 index in row
            const float4 v = *reinterpret_cast<const float4*>(
                x + (size_t)(m_cta + r) * K_DIM + kt + c4 * 4);
            As[r][c4 * 4 + 0] = v.x;
            As[r][c4 * 4 + 1] = v.y;
            As[r][c4 * 4 + 2] = v.z;
            As[r][c4 * 4 + 3] = v.w;
        }
        // ---- load B tile (fused binarize): W[N,K] row-major -> Bs[n][k] = ±alpha[n] ----
#pragma unroll
        for (int i = 0; i < 4; i++) {
            int f  = tid + i * 256;
            int r  = f >> 3;
            int c4 = f & 7;
            int n  = n_cta + r;
            float a = __ldg(alpha + n);
            const float4 v = *reinterpret_cast<const float4*>(
                W + (size_t)n * K_DIM + kt + c4 * 4);
            Bs[r][c4 * 4 + 0] = (v.x >= 0.0f) ? a : -a;
            Bs[r][c4 * 4 + 1] = (v.y >= 0.0f) ? a : -a;
            Bs[r][c4 * 4 + 2] = (v.z >= 0.0f) ? a : -a;
            Bs[r][c4 * 4 + 3] = (v.w >= 0.0f) ? a : -a;
        }
        __syncthreads();

        // ---- compute: 4 k-steps of m16n16k8 tf32 ----
#pragma unroll
        for (int kk = 0; kk < BK; kk += 8) {
            wmma::fragment<wmma::matrix_a, 16, 16, 8, wmma::precision::tf32,
                           wmma::row_major> af[4];
            wmma::fragment<wmma::matrix_b, 16, 16, 8, wmma::precision::tf32,
                           wmma::col_major> bf[2];
#pragma unroll
            for (int i = 0; i < 4; i++) {
                wmma::load_matrix_sync(af[i], &As[wm * 64 + i * 16][kk], SLD);
#pragma unroll
                for (int t = 0; t < af[i].num_elements; t++)
                    af[i].x[t] = wmma::__float_to_tf32(af[i].x[t]);
            }
#pragma unroll
            for (int j = 0; j < 2; j++) {
                // col_major B: element (k, n) at ptr[n*ldm + k]
                wmma::load_matrix_sync(bf[j], &Bs[wn * 32 + j * 16][kk], SLD);
#pragma unroll
                for (int t = 0; t < bf[j].num_elements; t++)
                    bf[j].x[t] = wmma::__float_to_tf32(bf[j].x[t]);
            }
#pragma unroll
            for (int i = 0; i < 4; i++)
#pragma unroll
                for (int j = 0; j < 2; j++)
                    wmma::mma_sync(c[i][j], af[i], bf[j], c[i][j]);
        }
        __syncthreads();
    }

    // ---- store accumulators (bias added by second kernel) ----
#pragma unroll
    for (int i = 0; i < 4; i++)
#pragma unroll
        for (int j = 0; j < 2; j++) {
            float* dst = out + (size_t)(m_cta + wm * 64 + i * 16) * N_DIM
                             + n_cta + wn * 32 + j * 16;
            wmma::store_matrix_sync(dst, c[i][j], N_DIM, wmma::mem_row_major);
        }
}

__global__ void add_bias(float* __restrict__ out,
                         const float* __restrict__ b, int nf4)
{
    int i = blockIdx.x * blockDim.x + threadIdx.x;
    if (i < nf4) {
        size_t idx = (size_t)i * 4;
        int o = (int)(idx & (N_DIM - 1));
        float4 v = *reinterpret_cast<float4*>(out + idx);
        v.x += __ldg(b + o + 0);
        v.y += __ldg(b + o + 1);
        v.z += __ldg(b + o + 2);
        v.w += __ldg(b + o + 3);
        *reinterpret_cast<float4*>(out + idx) = v;
    }
}

extern "C" void kernel_launch(void* const* d_in, const int* in_sizes, int n_in,
                              void* d_out, int out_size)
{
    const float* x     = (const float*)d_in[0];   // [M, 4096]
    const float* W     = (const float*)d_in[1];   // [4096, 4096]
    const float* alpha = (const float*)d_in[2];   // [4096, 1]
    const float* b     = (const float*)d_in[3];   // [4096]
    float* out = (float*)d_out;

    int M = in_sizes[0] / K_DIM;                  // 8192

    dim3 grid(N_DIM / BN, M / BM);                // (32, 64)
    bgemm_tf32<<<grid, 256>>>(x, W, alpha, out);

    int nf4 = out_size / 4;
    add_bias<<<(nf4 + 255) / 256, 256>>>(out, b, nf4);
}

// round 3
// speedup vs baseline: 2.4205x; 2.4205x over previous
#include <cuda_runtime.h>
#include <cstdint>

// BinaryLinear: out[M,N] = x[M,K] @ (sign(W)*alpha)[N,K]^T + b[N]
// M=8192, N=K=4096, fp32 in/out, tf32 mma.sync compute (legacy HMMA path --
// harness compiles for plain sm_100, so tcgen05 is unavailable).
//
// Pass 1: prep kernels -> g_xr = tf32-rounded x, g_bw = tf32(sign(W)*alpha).
// Pass 2: 4-stage cp.async pipelined GEMM, CTA tile 128x256, 8 warps,
//         warp tile 64x64, mma.sync.m16n8k8.tf32, fused bias epilogue.

#define K_DIM 4096
#define N_DIM 4096
#define M_MAX 8192
#define BM 128
#define BN 256
#define BK 32
#define NSTAGES 4
#define SLD 36                       // row stride in floats (BK + 4 pad)
#define A_STAGE_FLOATS (BM * SLD)    // 4608
#define B_STAGE_FLOATS (BN * SLD)    // 9216
#define STAGE_FLOATS (A_STAGE_FLOATS + B_STAGE_FLOATS)   // 13824
#define SMEM_BYTES (NSTAGES * STAGE_FLOATS * 4)          // 221184

// -------- device scratch --------
__device__ float g_xr[(size_t)M_MAX * K_DIM];
__device__ float g_bw[(size_t)N_DIM * K_DIM];

__device__ __forceinline__ uint32_t smem_u32(const void* p) {
    uint32_t a;
    asm("{ .reg .u64 t; cvta.to.shared.u64 t, %1; cvt.u32.u64 %0, t; }"
        : "=r"(a) : "l"(p));
    return a;
}

__device__ __forceinline__ float tf32_rna(float v) {
    uint32_t r;
    asm("cvt.rna.tf32.f32 %0, %1;" : "=r"(r) : "f"(v));
    return __uint_as_float(r);
}

// -------- prep kernels --------
__global__ void prep_x(const float* __restrict__ x, int n4) {
    int i = blockIdx.x * blockDim.x + threadIdx.x;
    if (i >= n4) return;
    float4 v = *reinterpret_cast<const float4*>(x + (size_t)i * 4);
    float4 o;
    o.x = tf32_rna(v.x); o.y = tf32_rna(v.y);
    o.z = tf32_rna(v.z); o.w = tf32_rna(v.w);
    *reinterpret_cast<float4*>(g_xr + (size_t)i * 4) = o;
}

__global__ void prep_w(const float* __restrict__ W,
                       const float* __restrict__ alpha, int n4) {
    int i = blockIdx.x * blockDim.x + threadIdx.x;
    if (i >= n4) return;
    float a = tf32_rna(__ldg(alpha + ((size_t)i * 4) / K_DIM));
    float4 v = *reinterpret_cast<const float4*>(W + (size_t)i * 4);
    float4 o;
    o.x = (v.x >= 0.0f) ? a : -a;
    o.y = (v.y >= 0.0f) ? a : -a;
    o.z = (v.z >= 0.0f) ? a : -a;
    o.w = (v.w >= 0.0f) ? a : -a;
    *reinterpret_cast<float4*>(g_bw + (size_t)i * 4) = o;
}

// -------- stage loader: 16B cp.async into padded SMEM --------
__device__ __forceinline__ void load_stage(uint32_t sb, int s, int kt,
                                           int m_cta, int n_cta) {
    const int tid = threadIdx.x;
    const uint32_t stA = sb + (uint32_t)s * (STAGE_FLOATS * 4);
    const uint32_t stB = stA + A_STAGE_FLOATS * 4;
#pragma unroll
    for (int k = 0; k < 4; k++) {                 // A: 1024 chunks (128 rows x 8)
        int c = tid + k * 256;
        int r = c >> 3, c4 = c & 7;
        uint32_t off = (uint32_t)(r * (SLD * 4) + c4 * 16);
        const void* src = (const void*)(g_xr + (size_t)(m_cta + r) * K_DIM + kt + c4 * 4);
        asm volatile("cp.async.cg.shared.global [%0], [%1], 16;\n"
                     :: "r"(stA + off), "l"(src));
    }
#pragma unroll
    for (int k = 0; k < 8; k++) {                 // B: 2048 chunks (256 rows x 8)
        int c = tid + k * 256;
        int r = c >> 3, c4 = c & 7;
        uint32_t off = (uint32_t)(r * (SLD * 4) + c4 * 16);
        const void* src = (const void*)(g_bw + (size_t)(n_cta + r) * K_DIM + kt + c4 * 4);
        asm volatile("cp.async.cg.shared.global [%0], [%1], 16;\n"
                     :: "r"(stB + off), "l"(src));
    }
}

__device__ __forceinline__ void mma_tf32(float* d, uint32_t a0, uint32_t a1,
                                         uint32_t a2, uint32_t a3,
                                         uint32_t b0, uint32_t b1) {
    asm volatile(
        "mma.sync.aligned.m16n8k8.row.col.f32.tf32.tf32.f32 "
        "{%0,%1,%2,%3}, {%4,%5,%6,%7}, {%8,%9}, {%0,%1,%2,%3};"
        : "+f"(d[0]), "+f"(d[1]), "+f"(d[2]), "+f"(d[3])
        : "r"(a0), "r"(a1), "r"(a2), "r"(a3), "r"(b0), "r"(b1));
}

// -------- main GEMM --------
__global__ __launch_bounds__(256, 1)
void bgemm(const float* __restrict__ bias, float* __restrict__ out) {
    extern __shared__ float smem[];
    const uint32_t sb = smem_u32(smem);
    const int tid  = threadIdx.x;
    const int wid  = tid >> 5;
    const int lane = tid & 31;
    const int g    = lane >> 2;       // group row 0..7
    const int c    = lane & 3;        // 0..3
    const int wm   = wid >> 2;        // 0..1 -> 64-row slab
    const int wn   = wid & 3;         // 0..3 -> 64-col slab
    const int m_cta = blockIdx.y * BM;
    const int n_cta = blockIdx.x * BN;

    float acc[4][8][4];
#pragma unroll
    for (int mt = 0; mt < 4; mt++)
#pragma unroll
        for (int nt = 0; nt < 8; nt++)
#pragma unroll
            for (int r = 0; r < 4; r++)
                acc[mt][nt][r] = 0.0f;

    // prologue: stages 0..2
#pragma unroll
    for (int s = 0; s < NSTAGES - 1; s++) {
        load_stage(sb, s, s * BK, m_cta, n_cta);
        asm volatile("cp.async.commit_group;\n");
    }

    const int NIT = K_DIM / BK;       // 128
    for (int i = 0; i < NIT; i++) {
        int j = i + NSTAGES - 1;
        if (j < NIT)
            load_stage(sb, j & (NSTAGES - 1), j * BK, m_cta, n_cta);
        asm volatile("cp.async.commit_group;\n");
        asm volatile("cp.async.wait_group %0;\n" :: "n"(NSTAGES - 1));
        __syncthreads();

        const int st = (i & (NSTAGES - 1)) * STAGE_FLOATS;
        const uint32_t* As = reinterpret_cast<const uint32_t*>(smem + st);
        const uint32_t* Bs = reinterpret_cast<const uint32_t*>(smem + st + A_STAGE_FLOATS);

#pragma unroll
        for (int s8 = 0; s8 < BK / 8; s8++) {
            const int k0 = s8 * 8;
            uint32_t a0[4], a1[4], a2[4], a3[4];
#pragma unroll
            for (int mt = 0; mt < 4; mt++) {
                int base = (wm * 64 + mt * 16 + g) * SLD + k0 + c;
                a0[mt] = As[base];
                a1[mt] = As[base + 8 * SLD];
                a2[mt] = As[base + 4];
                a3[mt] = As[base + 8 * SLD + 4];
            }
            uint32_t b0[8], b1[8];
#pragma unroll
            for (int nt = 0; nt < 8; nt++) {
                int base = (wn * 64 + nt * 8 + g) * SLD + k0 + c;
                b0[nt] = Bs[base];
                b1[nt] = Bs[base + 4];
            }
#pragma unroll
            for (int mt = 0; mt < 4; mt++)
#pragma unroll
                for (int nt = 0; nt < 8; nt++)
                    mma_tf32(acc[mt][nt], a0[mt], a1[mt], a2[mt], a3[mt],
                             b0[nt], b1[nt]);
        }
        __syncthreads();
    }

    // epilogue: fused bias, float2 stores (each lane-quad covers one 32B sector)
#pragma unroll
    for (int mt = 0; mt < 4; mt++) {
        const int rowA = m_cta + wm * 64 + mt * 16 + g;
        const int rowB = rowA + 8;
#pragma unroll
        for (int nt = 0; nt < 8; nt++) {
            const int col = n_cta + wn * 64 + nt * 8 + 2 * c;
            const float2 bv = *reinterpret_cast<const float2*>(bias + col);
            float2 v0, v1;
            v0.x = acc[mt][nt][0] + bv.x;
            v0.y = acc[mt][nt][1] + bv.y;
            v1.x = acc[mt][nt][2] + bv.x;
            v1.y = acc[mt][nt][3] + bv.y;
            *reinterpret_cast<float2*>(out + (size_t)rowA * N_DIM + col) = v0;
            *reinterpret_cast<float2*>(out + (size_t)rowB * N_DIM + col) = v1;
        }
    }
}

// -------- launch --------
extern "C" void kernel_launch(void* const* d_in, const int* in_sizes, int n_in,
                              void* d_out, int out_size) {
    const float* x     = (const float*)d_in[0];   // [M, 4096]
    const float* W     = (const float*)d_in[1];   // [4096, 4096]
    const float* alpha = (const float*)d_in[2];   // [4096, 1]
    const float* bias  = (const float*)d_in[3];   // [4096]
    float* out = (float*)d_out;

    const int M = in_sizes[0] / K_DIM;            // 8192

    int nx4 = (M * K_DIM) / 4;
    prep_x<<<(nx4 + 255) / 256, 256>>>(x, nx4);
    int nw4 = (N_DIM * K_DIM) / 4;
    prep_w<<<(nw4 + 255) / 256, 256>>>(W, alpha, nw4);

    cudaFuncSetAttribute(bgemm, cudaFuncAttributeMaxDynamicSharedMemorySize,
                         SMEM_BYTES);
    dim3 grid(N_DIM / BN, M / BM);                // (16, 64)
    bgemm<<<grid, 256, SMEM_BYTES>>>(bias, out);
}